// round 6
// baseline (speedup 1.0000x reference)
#include <cuda_runtime.h>
#include <math.h>
#include <stdint.h>

#define F   128
#define S   10
#define KC  16
#define MAXN 200000
#define MAXB 20000

typedef unsigned long long ull;

// static scratch (allocation-free rule)
__device__ float    g_pre[(size_t)MAXN * F];  // t_j * (q_j @ mask)
__device__ float    g_ln[MAXN];               // t_j . a_neigh
__device__ uint32_t g_wB[32 * 8 * 32 * 4];    // weight in tf32 B-fragment order

// ---- packed f32x2 helpers ----
__device__ __forceinline__ ull ffma2(ull a, ull b, ull c) {
    ull d; asm("fma.rn.f32x2 %0,%1,%2,%3;" : "=l"(d) : "l"(a), "l"(b), "l"(c)); return d;
}
__device__ __forceinline__ ull fmul2(ull a, ull b) {
    ull d; asm("mul.rn.f32x2 %0,%1,%2;" : "=l"(d) : "l"(a), "l"(b)); return d;
}
__device__ __forceinline__ ull fpack(float a, float b) {
    ull d; asm("mov.b64 %0,{%1,%2};" : "=l"(d) : "f"(a), "f"(b)); return d;
}
__device__ __forceinline__ float2 funpack(ull a) {
    float2 f; asm("mov.b64 {%0,%1},%2;" : "=f"(f.x), "=f"(f.y) : "l"(a)); return f;
}
__device__ __forceinline__ float fsum2(ull a) { float2 f = funpack(a); return f.x + f.y; }

__device__ __forceinline__ uint32_t tf32cvt(float x) {
    uint32_t u; asm("cvt.rna.tf32.f32 %0,%1;" : "=r"(u) : "f"(x)); return u;
}
__device__ __forceinline__ void mma_tf32(float* d, const uint32_t* a,
                                         uint32_t b0, uint32_t b1) {
    asm("mma.sync.aligned.m16n8k8.row.col.f32.tf32.tf32.f32 "
        "{%0,%1,%2,%3},{%4,%5,%6,%7},{%8,%9},{%0,%1,%2,%3};"
        : "+f"(d[0]), "+f"(d[1]), "+f"(d[2]), "+f"(d[3])
        : "r"(a[0]), "r"(a[1]), "r"(a[2]), "r"(a[3]), "r"(b0), "r"(b1));
}

// A-fragment scatter index for a 64x256 tile stored as [kt][mt][lane][slot]
__device__ __forceinline__ int frag_idx(int R, int C) {
    int mt = R >> 4, kt = C >> 3, r = R & 15, c = C & 7;
    int lane = ((r & 7) << 2) | (c & 3);
    int slot = (r >> 3) | ((c >> 2) << 1);
    return (((kt * 4 + mt) * 32 + lane) << 2) | slot;
}

// ---------------------------------------------------------------------------
// Kernel W: encode weight[128][256] into tf32 B-fragment order (one-time)
// g_wB[((kt*8 + ntp)*32 + lane)*4 + sub]:
//   nt = ntp*2 + (sub>>1); n = nt*8 + (lane>>2); k = kt*8 + (lane&3) + (sub&1)*4
// ---------------------------------------------------------------------------
__global__ void encode_w(const float* __restrict__ weight) {
    int idx = blockIdx.x * 256 + threadIdx.x;   // 32768 total
    int sub = idx & 3, lane = (idx >> 2) & 31;
    int ntp = (idx >> 7) & 7, kt = idx >> 10;
    int n = ntp * 16 + (sub >> 1) * 8 + (lane >> 2);
    int k = kt * 8 + (lane & 3) + (sub & 1) * 4;
    g_wB[idx] = tf32cvt(weight[n * 256 + k]);
}

// ---------------------------------------------------------------------------
// Kernel A: per-table-row precompute. grid = ceil(N/512), block = 256.
// Thread owns 2 full rows (tid, tid+256). x streamed from global in 16B
// chunks; center/mask reads are FULL-WARP broadcasts (1 wf per 4 ffma2).
// No cross-thread reductions.
// ---------------------------------------------------------------------------
__global__ void __launch_bounds__(256)
precompute_kernel(const float* __restrict__ neigh_table,
                  const float* __restrict__ center,
                  const float* __restrict__ cluster_mask,
                  const float* __restrict__ alpha,
                  int N) {
    __shared__ float s_C[2048], s_M[2048], s_an[128], s_c2[16];
    const int tid = threadIdx.x;

    #pragma unroll
    for (int e = tid; e < 512; e += 256) {
        ((float4*)s_C)[e] = ((const float4*)center)[e];
        ((float4*)s_M)[e] = ((const float4*)cluster_mask)[e];
    }
    if (tid < 32) ((float4*)s_an)[tid] = ((const float4*)alpha)[32 + tid];  // a_neigh
    __syncthreads();

    if (tid < KC) {
        float a = 0.f;
        #pragma unroll 8
        for (int f4 = 0; f4 < 32; f4++) {
            float4 c = *(const float4*)&s_C[tid * 128 + f4 * 4];
            a += c.x * c.x + c.y * c.y + c.z * c.z + c.w * c.w;
        }
        s_c2[tid] = a;
    }

    const int rowbase = blockIdx.x * 512;
    const int rA = min(rowbase + tid, N - 1);
    const int rB = min(rowbase + 256 + tid, N - 1);
    const float* pA = neigh_table + (size_t)rA * F;
    const float* pB = neigh_table + (size_t)rB * F;

    ull accA[KC], accB[KC];
    #pragma unroll
    for (int k = 0; k < KC; k++) { accA[k] = 0ull; accB[k] = 0ull; }
    ull n2A = 0ull, n2B = 0ull, lnA = 0ull, lnB = 0ull;

    ulonglong2 xA = *(const ulonglong2*)pA;     // 16B chunk (4 floats)
    ulonglong2 xB = *(const ulonglong2*)pB;
    #pragma unroll 4
    for (int ch = 0; ch < 32; ch++) {
        ulonglong2 nxA, nxB;
        if (ch < 31) {
            nxA = *(const ulonglong2*)(pA + (ch + 1) * 4);
            nxB = *(const ulonglong2*)(pB + (ch + 1) * 4);
        }
        ulonglong2 av = *(const ulonglong2*)&s_an[ch * 4];
        n2A = ffma2(xA.x, xA.x, n2A);  n2A = ffma2(xA.y, xA.y, n2A);
        n2B = ffma2(xB.x, xB.x, n2B);  n2B = ffma2(xB.y, xB.y, n2B);
        lnA = ffma2(xA.x, av.x, lnA);  lnA = ffma2(xA.y, av.y, lnA);
        lnB = ffma2(xB.x, av.x, lnB);  lnB = ffma2(xB.y, av.y, lnB);
        #pragma unroll
        for (int k = 0; k < KC; k++) {
            ulonglong2 c = *(const ulonglong2*)&s_C[k * 128 + ch * 4];  // bcast
            accA[k] = ffma2(xA.x, c.x, accA[k]);
            accA[k] = ffma2(xA.y, c.y, accA[k]);
            accB[k] = ffma2(xB.x, c.x, accB[k]);
            accB[k] = ffma2(xB.y, c.y, accB[k]);
        }
        xA = nxA;  xB = nxB;
    }

    __syncthreads();                            // s_c2 ready
    float n2fA = fsum2(n2A), n2fB = fsum2(n2B);
    g_ln[rA] = fsum2(lnA);                      // clamped dup rows: same value
    g_ln[rB] = fsum2(lnB);

    ull qqA[KC], qqB[KC];
    #pragma unroll
    for (int k = 0; k < KC; k++) {
        float c2k = s_c2[k] + 1.f;
        float qa = 1.f / (n2fA - 2.f * fsum2(accA[k]) + c2k);
        float qb = 1.f / (n2fB - 2.f * fsum2(accB[k]) + c2k);
        qqA[k] = fpack(qa, qa);
        qqB[k] = fpack(qb, qb);
    }

    // mask-MM + elementwise; x re-read (L2-hot)
    float* oA = g_pre + (size_t)rA * F;
    float* oB = g_pre + (size_t)rB * F;
    #pragma unroll 4
    for (int ch = 0; ch < 32; ch++) {
        ull mAx = 0ull, mAy = 0ull, mBx = 0ull, mBy = 0ull;
        #pragma unroll
        for (int k = 0; k < KC; k++) {
            ulonglong2 m = *(const ulonglong2*)&s_M[k * 128 + ch * 4];  // bcast
            mAx = ffma2(qqA[k], m.x, mAx);  mAy = ffma2(qqA[k], m.y, mAy);
            mBx = ffma2(qqB[k], m.x, mBx);  mBy = ffma2(qqB[k], m.y, mBy);
        }
        ulonglong2 xa = *(const ulonglong2*)(pA + ch * 4);
        ulonglong2 xb = *(const ulonglong2*)(pB + ch * 4);
        ulonglong2 pa, pb;
        pa.x = fmul2(xa.x, mAx);  pa.y = fmul2(xa.y, mAy);
        pb.x = fmul2(xb.x, mBx);  pb.y = fmul2(xb.y, mBy);
        *(ulonglong2*)(oA + ch * 4) = pa;
        *(ulonglong2*)(oB + ch * 4) = pb;
    }
}

// ---------------------------------------------------------------------------
// Kernel B: fused gather + attention + TF32 tensor GEMM.
// grid = ceil(B/64), block = 256. Phase 1 scatters the 64x256 comb tile into
// smem in mma A-fragment layout; phase 2: 8 warps x m16n8k8 tf32 MMA.
// ---------------------------------------------------------------------------
__global__ void __launch_bounds__(256)
fused_kernel(const int* __restrict__ nodes,
             const int* __restrict__ neigh_idx,
             const float* __restrict__ self_table,
             const float* __restrict__ alpha,
             float* __restrict__ out, int B) {
    extern __shared__ uint32_t smem_u[];
    uint32_t* sA      = smem_u;                 // 16384: A fragments
    float*    s_alpha = (float*)(smem_u + 16384);

    const int tid = threadIdx.x;
    if (tid < 32) ((float4*)s_alpha)[tid] = ((const float4*)alpha)[tid];  // a_self
    __syncthreads();

    const int m0 = blockIdx.x * 64;

    // ---- phase 1: gather + attention (4 threads/row, 32 floats each) ----
    {
        const int r = tid >> 2, qt = tid & 3;
        const int row = min(m0 + r, B - 1);
        const int node = nodes[row];
        const float4* sp = (const float4*)(self_table + (size_t)node * F + qt * 32);
        float4 sf[8];
        float lp = 0.f;
        #pragma unroll
        for (int j = 0; j < 8; j++) {
            sf[j] = sp[j];
            float4 av = *(const float4*)&s_alpha[qt * 32 + j * 4];
            lp += sf[j].x * av.x + sf[j].y * av.y + sf[j].z * av.z + sf[j].w * av.w;
        }
        lp += __shfl_xor_sync(0xffffffffu, lp, 1);
        lp += __shfl_xor_sync(0xffffffffu, lp, 2);

        int ji[S];
        #pragma unroll
        for (int s = 0; s < S; s++) ji[s] = neigh_idx[row * S + s];
        float att[S], asum = 0.f;
        #pragma unroll
        for (int s = 0; s < S; s++) {
            float l = fmaxf(lp + g_ln[ji[s]], 0.f);
            att[s] = __expf(l);
            asum += att[s];
        }
        const float inv = 1.f / asum;

        float4 agg[8];
        #pragma unroll
        for (int j = 0; j < 8; j++) agg[j] = make_float4(0.f, 0.f, 0.f, 0.f);
        #pragma unroll
        for (int s = 0; s < S; s++) {
            const float w = att[s] * inv;
            const float4* pp = (const float4*)(g_pre + (size_t)ji[s] * F + qt * 32);
            #pragma unroll
            for (int j = 0; j < 8; j++) {
                float4 v = pp[j];
                agg[j].x += w * v.x;  agg[j].y += w * v.y;
                agg[j].z += w * v.z;  agg[j].w += w * v.w;
            }
        }

        // scatter into fragment layout (tf32-converted)
        #pragma unroll
        for (int j = 0; j < 8; j++) {
            int c0 = qt * 32 + j * 4;
            sA[frag_idx(r, c0 + 0)] = tf32cvt(sf[j].x);
            sA[frag_idx(r, c0 + 1)] = tf32cvt(sf[j].y);
            sA[frag_idx(r, c0 + 2)] = tf32cvt(sf[j].z);
            sA[frag_idx(r, c0 + 3)] = tf32cvt(sf[j].w);
            sA[frag_idx(r, 128 + c0 + 0)] = tf32cvt(agg[j].x);
            sA[frag_idx(r, 128 + c0 + 1)] = tf32cvt(agg[j].y);
            sA[frag_idx(r, 128 + c0 + 2)] = tf32cvt(agg[j].z);
            sA[frag_idx(r, 128 + c0 + 3)] = tf32cvt(agg[j].w);
        }
    }
    __syncthreads();

    // ---- phase 2: TF32 MMA. warp = (wm: M-half 32) x (wn: N-quarter 32) ----
    {
        const int lane = tid & 31, w = tid >> 5;
        const int wm = w & 1, wn = w >> 1;
        float d[2][4][4];
        #pragma unroll
        for (int mt = 0; mt < 2; mt++)
            #pragma unroll
            for (int nt = 0; nt < 4; nt++)
                #pragma unroll
                for (int i = 0; i < 4; i++) d[mt][nt][i] = 0.f;

        #pragma unroll 2
        for (int kt = 0; kt < 32; kt++) {
            uint4 a0 = *(const uint4*)&sA[((kt * 4 + wm * 2 + 0) * 32 + lane) * 4];
            uint4 a1 = *(const uint4*)&sA[((kt * 4 + wm * 2 + 1) * 32 + lane) * 4];
            uint4 bA = *(const uint4*)&g_wB[((kt * 8 + wn * 2 + 0) * 32 + lane) * 4];
            uint4 bB = *(const uint4*)&g_wB[((kt * 8 + wn * 2 + 1) * 32 + lane) * 4];
            mma_tf32(d[0][0], (const uint32_t*)&a0, bA.x, bA.y);
            mma_tf32(d[0][1], (const uint32_t*)&a0, bA.z, bA.w);
            mma_tf32(d[0][2], (const uint32_t*)&a0, bB.x, bB.y);
            mma_tf32(d[0][3], (const uint32_t*)&a0, bB.z, bB.w);
            mma_tf32(d[1][0], (const uint32_t*)&a1, bA.x, bA.y);
            mma_tf32(d[1][1], (const uint32_t*)&a1, bA.z, bA.w);
            mma_tf32(d[1][2], (const uint32_t*)&a1, bB.x, bB.y);
            mma_tf32(d[1][3], (const uint32_t*)&a1, bB.z, bB.w);
        }

        #pragma unroll
        for (int mt = 0; mt < 2; mt++) {
            #pragma unroll
            for (int nt = 0; nt < 4; nt++) {
                int R = wm * 32 + mt * 16 + (lane >> 2);
                int C = wn * 32 + nt * 8 + (lane & 3) * 2;
                int m = m0 + R;
                if (m < B) {
                    float2 o;
                    o.x = fmaxf(d[mt][nt][0], 0.f);
                    o.y = fmaxf(d[mt][nt][1], 0.f);
                    *(float2*)&out[(size_t)m * F + C] = o;
                }
                if (m + 8 < B) {
                    float2 o;
                    o.x = fmaxf(d[mt][nt][2], 0.f);
                    o.y = fmaxf(d[mt][nt][3], 0.f);
                    *(float2*)&out[(size_t)(m + 8) * F + C] = o;
                }
            }
        }
    }
}

#define FUSED_SMEM (16384 * 4 + 128 * 4)

// ---------------------------------------------------------------------------
extern "C" void kernel_launch(void* const* d_in, const int* in_sizes, int n_in,
                              void* d_out, int out_size) {
    const int*   nodes        = (const int*)d_in[0];
    const int*   neigh_idx    = (const int*)d_in[1];
    const float* self_table   = (const float*)d_in[2];
    const float* neigh_table  = (const float*)d_in[3];
    const float* center       = (const float*)d_in[4];
    const float* cluster_mask = (const float*)d_in[5];
    const float* weight       = (const float*)d_in[6];
    const float* alpha        = (const float*)d_in[7];
    float* out = (float*)d_out;

    int B = in_sizes[0];
    int N = in_sizes[3] / F;

    cudaFuncSetAttribute(fused_kernel,
                         cudaFuncAttributeMaxDynamicSharedMemorySize, FUSED_SMEM);

    encode_w<<<128, 256>>>(weight);
    precompute_kernel<<<(N + 511) / 512, 256>>>(neigh_table, center,
                                                cluster_mask, alpha, N);
    fused_kernel<<<(B + 63) / 64, 256, FUSED_SMEM>>>(nodes, neigh_idx,
                                                     self_table, alpha, out, B);
}

// round 7
// speedup vs baseline: 1.4092x; 1.4092x over previous
#include <cuda_runtime.h>
#include <math.h>
#include <stdint.h>

#define F   128
#define S   10
#define KC  16
#define MAXN 200000
#define MAXB 20000

typedef unsigned long long ull;

// static scratch (allocation-free rule)
__device__ float    g_pre[(size_t)MAXN * F];  // t_j * (q_j @ mask)
__device__ float    g_ln[MAXN];               // t_j . a_neigh
__device__ uint32_t g_wB[32 * 8 * 32 * 4];    // weight in tf32 B-fragment order

// ---- packed f32x2 helpers ----
__device__ __forceinline__ ull ffma2(ull a, ull b, ull c) {
    ull d; asm("fma.rn.f32x2 %0,%1,%2,%3;" : "=l"(d) : "l"(a), "l"(b), "l"(c)); return d;
}
__device__ __forceinline__ ull fmul2(ull a, ull b) {
    ull d; asm("mul.rn.f32x2 %0,%1,%2;" : "=l"(d) : "l"(a), "l"(b)); return d;
}
__device__ __forceinline__ ull fpack(float a, float b) {
    ull d; asm("mov.b64 %0,{%1,%2};" : "=l"(d) : "f"(a), "f"(b)); return d;
}
__device__ __forceinline__ float2 funpack(ull a) {
    float2 f; asm("mov.b64 {%0,%1},%2;" : "=f"(f.x), "=f"(f.y) : "l"(a)); return f;
}
__device__ __forceinline__ float fsum2(ull a) { float2 f = funpack(a); return f.x + f.y; }

__device__ __forceinline__ uint32_t tf32cvt(float x) {
    uint32_t u; asm("cvt.rna.tf32.f32 %0,%1;" : "=r"(u) : "f"(x)); return u;
}
__device__ __forceinline__ void mma_tf32(float* d, const uint32_t* a,
                                         uint32_t b0, uint32_t b1) {
    asm("mma.sync.aligned.m16n8k8.row.col.f32.tf32.tf32.f32 "
        "{%0,%1,%2,%3},{%4,%5,%6,%7},{%8,%9},{%0,%1,%2,%3};"
        : "+f"(d[0]), "+f"(d[1]), "+f"(d[2]), "+f"(d[3])
        : "r"(a[0]), "r"(a[1]), "r"(a[2]), "r"(a[3]), "r"(b0), "r"(b1));
}

// ---------------------------------------------------------------------------
// Kernel W: encode weight[128][256] into tf32 B-fragment order (verified R6)
// ---------------------------------------------------------------------------
__global__ void encode_w(const float* __restrict__ weight) {
    int idx = blockIdx.x * 256 + threadIdx.x;   // 32768 total
    int sub = idx & 3, lane = (idx >> 2) & 31;
    int ntp = (idx >> 7) & 7, kt = idx >> 10;
    int n = ntp * 16 + (sub >> 1) * 8 + (lane >> 2);
    int k = kt * 8 + (lane & 3) + (sub & 1) * 4;
    g_wB[idx] = tf32cvt(weight[n * 256 + k]);
}

// ---------------------------------------------------------------------------
// Kernel A: per-table-row precompute (verified R5). grid=ceil(N/128), blk=256.
// ---------------------------------------------------------------------------
#define TS  136
#define HOF 68

__global__ void __launch_bounds__(256, 2)
precompute_kernel(const float* __restrict__ neigh_table,
                  const float* __restrict__ center,
                  const float* __restrict__ cluster_mask,
                  const float* __restrict__ alpha,
                  int N) {
    extern __shared__ float sm[];
    float* s_T  = sm;                 // [128][TS]
    float* s_C  = s_T + 128 * TS;     // [16][TS] (half layout)
    float* s_M  = s_C + KC * TS;      // [16][TS]
    float* s_an = s_M + KC * TS;      // [TS]
    float* s_c2 = s_an + TS;          // [16]

    const int tid = threadIdx.x;
    const int rowbase = blockIdx.x * 128;

    #pragma unroll
    for (int e = tid; e < 512; e += 256) {                // 512 float4
        int k = e >> 5, c4 = e & 31;
        int dst = k * TS + (c4 >> 4) * HOF + (c4 & 15) * 4;
        *(float4*)&s_C[dst] = ((const float4*)center)[e];
        *(float4*)&s_M[dst] = ((const float4*)cluster_mask)[e];
    }
    if (tid < 32) {
        int dst = (tid >> 4) * HOF + (tid & 15) * 4;
        *(float4*)&s_an[dst] = ((const float4*)alpha)[32 + tid];  // a_neigh
    }

    #pragma unroll
    for (int it = 0; it < 16; it++) {
        int e = it * 256 + tid;
        int r = e >> 5, c4 = e & 31;
        int grow = min(rowbase + r, N - 1);
        float4 v = *(const float4*)&neigh_table[(size_t)grow * F + c4 * 4];
        *(float4*)&s_T[r * TS + (c4 >> 4) * HOF + (c4 & 15) * 4] = v;
    }
    __syncthreads();

    if (tid < KC) {
        float a = 0.f;
        #pragma unroll
        for (int hh = 0; hh < 2; hh++)
            #pragma unroll 4
            for (int j = 0; j < 16; j++) {
                float4 c = *(const float4*)&s_C[tid * TS + hh * HOF + j * 4];
                a += c.x * c.x + c.y * c.y + c.z * c.z + c.w * c.w;
            }
        s_c2[tid] = a;
    }

    const int rl = tid >> 1, h = tid & 1;
    const int grow = min(rowbase + rl, N - 1);
    const float* xb = &s_T[rl * TS + h * HOF];
    const float* ab = &s_an[h * HOF];

    ull acc[KC];
    #pragma unroll
    for (int k = 0; k < KC; k++) acc[k] = 0ull;
    ull n2 = 0ull, ln = 0ull;

    #pragma unroll 4
    for (int ch = 0; ch < 16; ch++) {
        ulonglong2 x = *(const ulonglong2*)&xb[ch * 4];
        ulonglong2 a = *(const ulonglong2*)&ab[ch * 4];
        n2 = ffma2(x.x, x.x, n2);  n2 = ffma2(x.y, x.y, n2);
        ln = ffma2(x.x, a.x, ln);  ln = ffma2(x.y, a.y, ln);
        #pragma unroll
        for (int k = 0; k < KC; k++) {
            ulonglong2 c = *(const ulonglong2*)&s_C[k * TS + h * HOF + ch * 4];
            acc[k] = ffma2(x.x, c.x, acc[k]);
            acc[k] = ffma2(x.y, c.y, acc[k]);
        }
    }

    float n2f = fsum2(n2), lnf = fsum2(ln);
    n2f += __shfl_xor_sync(0xffffffffu, n2f, 1);
    lnf += __shfl_xor_sync(0xffffffffu, lnf, 1);
    if (h == 0) g_ln[grow] = lnf;

    float crs[KC];
    #pragma unroll
    for (int k = 0; k < KC; k++) {
        crs[k] = fsum2(acc[k]);
        crs[k] += __shfl_xor_sync(0xffffffffu, crs[k], 1);
    }

    __syncthreads();
    ull qq[KC];
    #pragma unroll
    for (int k = 0; k < KC; k++) {
        float q = 1.f / (n2f - 2.f * crs[k] + s_c2[k] + 1.f);
        qq[k] = fpack(q, q);
    }

    float* op = g_pre + (size_t)grow * F + h * 64;
    #pragma unroll 4
    for (int ch = 0; ch < 16; ch++) {
        ull mx = 0ull, my = 0ull;
        #pragma unroll
        for (int k = 0; k < KC; k++) {
            ulonglong2 m = *(const ulonglong2*)&s_M[k * TS + h * HOF + ch * 4];
            mx = ffma2(qq[k], m.x, mx);
            my = ffma2(qq[k], m.y, my);
        }
        ulonglong2 x = *(const ulonglong2*)&xb[ch * 4];
        ulonglong2 p;
        p.x = fmul2(x.x, mx);
        p.y = fmul2(x.y, my);
        *(ulonglong2*)&op[ch * 4] = p;
    }
}

#define A_SMEM ((128 * TS + 2 * KC * TS + TS + KC) * 4)

// ---------------------------------------------------------------------------
// Kernel B: fused gather + attention + TF32 MMA GEMM. grid=ceil(B/32), blk=256.
// Phase 1: 8 thr/row, sector-clean 64B gathers, comb tile written PLAIN to
// smem (tf32-converted bits), stride 268 -> phase-2 A reads conflict-free.
// Phase 2: 8 warps, each warp owns 16 output cols x all 32 rows; A-fragments
// loaded directly from the plain tile (no scatter); B from g_wB (verified).
// ---------------------------------------------------------------------------
#define CS 268

__global__ void __launch_bounds__(256, 3)
fused_kernel(const int* __restrict__ nodes,
             const int* __restrict__ neigh_idx,
             const float* __restrict__ self_table,
             const float* __restrict__ alpha,
             float* __restrict__ out, int B) {
    extern __shared__ float smf[];
    float* s_comb  = smf;             // [32][CS] tf32-bit floats
    float* s_alpha = smf + 32 * CS;   // [128]

    const int tid = threadIdx.x;
    if (tid < 32) ((float4*)s_alpha)[tid] = ((const float4*)alpha)[tid];  // a_self
    __syncthreads();

    const int m0 = blockIdx.x * 32;

    // ---- phase 1: gather + attention ----
    {
        const int r = tid >> 3, g = tid & 7;
        const int row = min(m0 + r, B - 1);
        const int node = nodes[row];
        const float4* sp = (const float4*)(self_table + (size_t)node * F + g * 16);
        float4 sf[4];
        float lp = 0.f;
        #pragma unroll
        for (int j = 0; j < 4; j++) {
            sf[j] = sp[j];
            float4 av = *(const float4*)&s_alpha[g * 16 + j * 4];
            lp += sf[j].x * av.x + sf[j].y * av.y + sf[j].z * av.z + sf[j].w * av.w;
        }
        lp += __shfl_xor_sync(0xffffffffu, lp, 1);
        lp += __shfl_xor_sync(0xffffffffu, lp, 2);
        lp += __shfl_xor_sync(0xffffffffu, lp, 4);

        int ji[S];
        #pragma unroll
        for (int s = 0; s < S; s++) ji[s] = neigh_idx[row * S + s];
        float att[S], asum = 0.f;
        #pragma unroll
        for (int s = 0; s < S; s++) {
            float l = fmaxf(lp + g_ln[ji[s]], 0.f);
            att[s] = __expf(l);
            asum += att[s];
        }
        const float inv = 1.f / asum;

        float4 agg[4];
        #pragma unroll
        for (int j = 0; j < 4; j++) agg[j] = make_float4(0.f, 0.f, 0.f, 0.f);
        #pragma unroll
        for (int s = 0; s < S; s++) {
            const float w = att[s] * inv;
            const float4* pp = (const float4*)(g_pre + (size_t)ji[s] * F + g * 16);
            #pragma unroll
            for (int j = 0; j < 4; j++) {
                float4 v = pp[j];
                agg[j].x += w * v.x;  agg[j].y += w * v.y;
                agg[j].z += w * v.z;  agg[j].w += w * v.w;
            }
        }

        // plain tile write, tf32-converted bits
        #pragma unroll
        for (int j = 0; j < 4; j++) {
            float4 a, b;
            a.x = __uint_as_float(tf32cvt(sf[j].x));
            a.y = __uint_as_float(tf32cvt(sf[j].y));
            a.z = __uint_as_float(tf32cvt(sf[j].z));
            a.w = __uint_as_float(tf32cvt(sf[j].w));
            b.x = __uint_as_float(tf32cvt(agg[j].x));
            b.y = __uint_as_float(tf32cvt(agg[j].y));
            b.z = __uint_as_float(tf32cvt(agg[j].z));
            b.w = __uint_as_float(tf32cvt(agg[j].w));
            *(float4*)&s_comb[r * CS + g * 16 + j * 4]       = a;
            *(float4*)&s_comb[r * CS + 128 + g * 16 + j * 4] = b;
        }
    }
    __syncthreads();

    // ---- phase 2: TF32 MMA. warp w owns cols [w*16, w*16+16), rows 0..31 ----
    {
        const int lane = tid & 31, w = tid >> 5;
        float d[2][2][4];
        #pragma unroll
        for (int mt = 0; mt < 2; mt++)
            #pragma unroll
            for (int nt = 0; nt < 2; nt++)
                #pragma unroll
                for (int i = 0; i < 4; i++) d[mt][nt][i] = 0.f;

        const uint32_t* wB = &g_wB[((size_t)w * 32 + lane) * 4];
        const int arow = lane >> 2, acol = lane & 3;

        #pragma unroll 4
        for (int kt = 0; kt < 32; kt++) {
            uint4 b = *(const uint4*)(wB + (size_t)kt * 1024);
            const int kc = kt * 8 + acol;
            #pragma unroll
            for (int mt = 0; mt < 2; mt++) {
                const float* ap = &s_comb[(mt * 16 + arow) * CS + kc];
                uint32_t a[4];
                a[0] = __float_as_uint(ap[0]);
                a[1] = __float_as_uint(ap[8 * CS]);
                a[2] = __float_as_uint(ap[4]);
                a[3] = __float_as_uint(ap[8 * CS + 4]);
                mma_tf32(d[mt][0], a, b.x, b.y);
                mma_tf32(d[mt][1], a, b.z, b.w);
            }
        }

        #pragma unroll
        for (int mt = 0; mt < 2; mt++) {
            #pragma unroll
            for (int nt = 0; nt < 2; nt++) {
                int R = mt * 16 + (lane >> 2);
                int C = w * 16 + nt * 8 + (lane & 3) * 2;
                int m = m0 + R;
                if (m < B) {
                    float2 o;
                    o.x = fmaxf(d[mt][nt][0], 0.f);
                    o.y = fmaxf(d[mt][nt][1], 0.f);
                    *(float2*)&out[(size_t)m * F + C] = o;
                }
                if (m + 8 < B) {
                    float2 o;
                    o.x = fmaxf(d[mt][nt][2], 0.f);
                    o.y = fmaxf(d[mt][nt][3], 0.f);
                    *(float2*)&out[(size_t)(m + 8) * F + C] = o;
                }
            }
        }
    }
}

#define FUSED_SMEM ((32 * CS + 128) * 4)

// ---------------------------------------------------------------------------
extern "C" void kernel_launch(void* const* d_in, const int* in_sizes, int n_in,
                              void* d_out, int out_size) {
    const int*   nodes        = (const int*)d_in[0];
    const int*   neigh_idx    = (const int*)d_in[1];
    const float* self_table   = (const float*)d_in[2];
    const float* neigh_table  = (const float*)d_in[3];
    const float* center       = (const float*)d_in[4];
    const float* cluster_mask = (const float*)d_in[5];
    const float* weight       = (const float*)d_in[6];
    const float* alpha        = (const float*)d_in[7];
    float* out = (float*)d_out;

    int B = in_sizes[0];
    int N = in_sizes[3] / F;

    cudaFuncSetAttribute(precompute_kernel,
                         cudaFuncAttributeMaxDynamicSharedMemorySize, A_SMEM);
    cudaFuncSetAttribute(fused_kernel,
                         cudaFuncAttributeMaxDynamicSharedMemorySize, FUSED_SMEM);

    encode_w<<<128, 256>>>(weight);
    precompute_kernel<<<(N + 127) / 128, 256, A_SMEM>>>(neigh_table, center,
                                                        cluster_mask, alpha, N);
    fused_kernel<<<(B + 31) / 32, 256, FUSED_SMEM>>>(nodes, neigh_idx,
                                                     self_table, alpha, out, B);
}

// round 8
// speedup vs baseline: 1.7927x; 1.2721x over previous
#include <cuda_runtime.h>
#include <math.h>
#include <stdint.h>

#define F   128
#define S   10
#define KC  16
#define MAXN 200000
#define MAXB 20000

typedef unsigned long long ull;

// static scratch (allocation-free rule)
__device__ float    g_pre[(size_t)MAXN * F];  // t_j * (q_j @ mask)
__device__ float    g_ln[MAXN];               // t_j . a_neigh
__device__ uint32_t g_wB[32 * 8 * 32 * 4];    // weight tf32 B-frags (out GEMM)
__device__ uint32_t g_cB[16 * 32 * 4];        // center tf32 B-frags (cross)
__device__ uint32_t g_mB[16 * 32 * 4];        // mask tf32 B-frags (maskMM)
__device__ float    g_c2[16];                 // |center_k|^2

// ---- packed f32x2 helpers ----
__device__ __forceinline__ ull ffma2(ull a, ull b, ull c) {
    ull d; asm("fma.rn.f32x2 %0,%1,%2,%3;" : "=l"(d) : "l"(a), "l"(b), "l"(c)); return d;
}
__device__ __forceinline__ float2 funpack(ull a) {
    float2 f; asm("mov.b64 {%0,%1},%2;" : "=f"(f.x), "=f"(f.y) : "l"(a)); return f;
}
__device__ __forceinline__ float fsum2(ull a) { float2 f = funpack(a); return f.x + f.y; }

__device__ __forceinline__ uint32_t tf32cvt(float x) {
    uint32_t u; asm("cvt.rna.tf32.f32 %0,%1;" : "=r"(u) : "f"(x)); return u;
}
__device__ __forceinline__ void mma_tf32(float* d, const uint32_t* a,
                                         uint32_t b0, uint32_t b1) {
    asm("mma.sync.aligned.m16n8k8.row.col.f32.tf32.tf32.f32 "
        "{%0,%1,%2,%3},{%4,%5,%6,%7},{%8,%9},{%0,%1,%2,%3};"
        : "+f"(d[0]), "+f"(d[1]), "+f"(d[2]), "+f"(d[3])
        : "r"(a[0]), "r"(a[1]), "r"(a[2]), "r"(a[3]), "r"(b0), "r"(b1));
}

// ---------------------------------------------------------------------------
// Kernel E: encode all constants (weight/center/mask B-frags + c2). One-time.
// tasks: [0,32768) wB | [32768,34816) cB | [34816,36864) mB | [36864,36880) c2
// ---------------------------------------------------------------------------
__global__ void encode_consts(const float* __restrict__ weight,
                              const float* __restrict__ center,
                              const float* __restrict__ cluster_mask) {
    int idx = blockIdx.x * 256 + threadIdx.x;
    if (idx < 32768) {                      // weight B-frags (verified R6)
        int sub = idx & 3, lane = (idx >> 2) & 31;
        int ntp = (idx >> 7) & 7, kt = idx >> 10;
        int n = ntp * 16 + (sub >> 1) * 8 + (lane >> 2);
        int k = kt * 8 + (lane & 3) + (sub & 1) * 4;
        g_wB[idx] = tf32cvt(weight[n * 256 + k]);
    } else if (idx < 34816) {               // center B-frags: b = C[n][k]
        int j = idx - 32768;
        int sub = j & 3, lane = (j >> 2) & 31, kt = j >> 7;   // kt 0..15
        int n = (sub >> 1) * 8 + (lane >> 2);                 // nt = sub>>1
        int k = kt * 8 + (lane & 3) + (sub & 1) * 4;
        g_cB[j] = tf32cvt(center[n * F + k]);
    } else if (idx < 36864) {               // mask B-frags: b = mask[k][n]
        int j = idx - 34816;
        int sub = j & 3, lane = (j >> 2) & 31, nt = j >> 7;   // nt 0..15
        int n = nt * 8 + (lane >> 2);
        int k = (sub >> 1) * 8 + (lane & 3) + (sub & 1) * 4;  // kt = sub>>1
        g_mB[j] = tf32cvt(cluster_mask[k * F + n]);
    } else if (idx < 36880) {               // c2
        int k = idx - 36864;
        float a = 0.f;
        for (int f = 0; f < F; f++) { float c = center[k * F + f]; a += c * c; }
        g_c2[k] = a;
    }
}

// ---------------------------------------------------------------------------
// Kernel A: precompute via tensor cores. grid = ceil(N/128), block = 256.
// Warp w owns M-strip rows [w*16, w*16+16). cross & maskMM on tf32 MMA;
// n2/ln fp32. A-frags load conflict-free from plain s_T (stride 132).
// ---------------------------------------------------------------------------
#define PTS 132

__global__ void __launch_bounds__(256, 2)
precompute_kernel(const float* __restrict__ neigh_table,
                  const float* __restrict__ alpha,
                  int N) {
    extern __shared__ float sm[];
    float*    s_T  = sm;                    // [128][PTS]
    float*    s_an = sm + 128 * PTS;        // [128]
    float*    s_n2 = s_an + 128;            // [128]
    float*    s_c2 = s_n2 + 128;            // [16]
    uint32_t* s_Q  = (uint32_t*)(s_c2 + 16);// [128][20] tf32 bits

    const int tid = threadIdx.x;
    const int rowbase = blockIdx.x * 128;

    if (tid < 32) ((float4*)s_an)[tid] = ((const float4*)alpha)[32 + tid];  // a_neigh
    if (tid < 16) s_c2[tid] = g_c2[tid];

    #pragma unroll
    for (int it = 0; it < 16; it++) {       // coalesced tile load
        int e = it * 256 + tid;
        int r = e >> 5, c4 = e & 31;
        int grow = min(rowbase + r, N - 1);
        float4 v = *(const float4*)&neigh_table[(size_t)grow * F + c4 * 4];
        *(float4*)&s_T[r * PTS + c4 * 4] = v;
    }
    __syncthreads();

    // ---- n2 / ln (fp32): thread = (row tid>>1, half tid&1) ----
    {
        const int r = tid >> 1, h = tid & 1;
        const float* xb = &s_T[r * PTS + h * 64];
        const float* ab = &s_an[h * 64];
        ull n2 = 0ull, ln = 0ull;
        #pragma unroll 4
        for (int ch = 0; ch < 16; ch++) {
            ulonglong2 x = *(const ulonglong2*)&xb[ch * 4];
            ulonglong2 a = *(const ulonglong2*)&ab[ch * 4];
            n2 = ffma2(x.x, x.x, n2);  n2 = ffma2(x.y, x.y, n2);
            ln = ffma2(x.x, a.x, ln);  ln = ffma2(x.y, a.y, ln);
        }
        float n2f = fsum2(n2), lnf = fsum2(ln);
        n2f += __shfl_xor_sync(0xffffffffu, n2f, 1);
        lnf += __shfl_xor_sync(0xffffffffu, lnf, 1);
        if (h == 0) {
            s_n2[r] = n2f;
            g_ln[min(rowbase + r, N - 1)] = lnf;
        }
    }

    const int l = tid & 31, w = tid >> 5;
    const int r0 = w * 16 + (l >> 2);       // lane row (and r0+8)
    const int c  = l & 3;

    // ---- cross = T @ C^T via MMA: 16 kt, N=16 (2 n-tiles) ----
    float d[2][4];
    #pragma unroll
    for (int nt = 0; nt < 2; nt++)
        #pragma unroll
        for (int i = 0; i < 4; i++) d[nt][i] = 0.f;

    #pragma unroll 4
    for (int kt = 0; kt < 16; kt++) {
        uint4 bc = *(const uint4*)&g_cB[(kt * 32 + l) * 4];
        const float* ap = &s_T[r0 * PTS + kt * 8 + c];
        uint32_t a[4];
        a[0] = tf32cvt(ap[0]);
        a[1] = tf32cvt(ap[8 * PTS]);
        a[2] = tf32cvt(ap[4]);
        a[3] = tf32cvt(ap[8 * PTS + 4]);
        mma_tf32(d[0], a, bc.x, bc.y);
        mma_tf32(d[1], a, bc.z, bc.w);
    }
    __syncthreads();                        // s_n2 ready

    // ---- q epilogue -> s_Q (tf32 bits), rows owned by this warp ----
    {
        const float n2A = s_n2[r0], n2B = s_n2[r0 + 8];
        #pragma unroll
        for (int nt = 0; nt < 2; nt++) {
            int k0 = nt * 8 + 2 * c;
            float c2a = s_c2[k0] + 1.f, c2b = s_c2[k0 + 1] + 1.f;
            uint2 qa, qb;
            qa.x = tf32cvt(1.f / (n2A - 2.f * d[nt][0] + c2a));
            qa.y = tf32cvt(1.f / (n2A - 2.f * d[nt][1] + c2b));
            qb.x = tf32cvt(1.f / (n2B - 2.f * d[nt][2] + c2a));
            qb.y = tf32cvt(1.f / (n2B - 2.f * d[nt][3] + c2b));
            *(uint2*)&s_Q[r0 * 20 + k0]       = qa;
            *(uint2*)&s_Q[(r0 + 8) * 20 + k0] = qb;
        }
    }
    __syncwarp();

    // ---- maskMM A-frags (q), K=16 -> 2 kt ----
    uint32_t aq[2][4];
    #pragma unroll
    for (int kt = 0; kt < 2; kt++) {
        aq[kt][0] = s_Q[r0 * 20 + kt * 8 + c];
        aq[kt][1] = s_Q[(r0 + 8) * 20 + kt * 8 + c];
        aq[kt][2] = s_Q[r0 * 20 + kt * 8 + c + 4];
        aq[kt][3] = s_Q[(r0 + 8) * 20 + kt * 8 + c + 4];
    }

    const int growA = min(rowbase + r0, N - 1);
    const int growB = min(rowbase + r0 + 8, N - 1);

    // ---- m = q @ mask via MMA; pre = T * m; store ----
    #pragma unroll 4
    for (int nt = 0; nt < 16; nt++) {
        uint4 bm = *(const uint4*)&g_mB[(nt * 32 + l) * 4];
        float dm[4] = {0.f, 0.f, 0.f, 0.f};
        mma_tf32(dm, aq[0], bm.x, bm.y);
        mma_tf32(dm, aq[1], bm.z, bm.w);

        int col = nt * 8 + 2 * c;
        float2 tA = *(const float2*)&s_T[r0 * PTS + col];
        float2 tB = *(const float2*)&s_T[(r0 + 8) * PTS + col];
        float2 oA, oB;
        oA.x = tA.x * dm[0];  oA.y = tA.y * dm[1];
        oB.x = tB.x * dm[2];  oB.y = tB.y * dm[3];
        *(float2*)&g_pre[(size_t)growA * F + col] = oA;
        *(float2*)&g_pre[(size_t)growB * F + col] = oB;
    }
}

#define A_SMEM ((128 * PTS + 128 + 128 + 16 + 128 * 20) * 4)

// ---------------------------------------------------------------------------
// Kernel B: fused gather + attention + TF32 MMA GEMM (verified R7).
// ---------------------------------------------------------------------------
#define CS 268

__global__ void __launch_bounds__(256, 3)
fused_kernel(const int* __restrict__ nodes,
             const int* __restrict__ neigh_idx,
             const float* __restrict__ self_table,
             const float* __restrict__ alpha,
             float* __restrict__ out, int B) {
    extern __shared__ float smf[];
    float* s_comb  = smf;             // [32][CS] tf32-bit floats
    float* s_alpha = smf + 32 * CS;   // [128]

    const int tid = threadIdx.x;
    if (tid < 32) ((float4*)s_alpha)[tid] = ((const float4*)alpha)[tid];  // a_self
    __syncthreads();

    const int m0 = blockIdx.x * 32;

    // ---- phase 1: gather + attention ----
    {
        const int r = tid >> 3, g = tid & 7;
        const int row = min(m0 + r, B - 1);
        const int node = nodes[row];
        const float4* sp = (const float4*)(self_table + (size_t)node * F + g * 16);
        float4 sf[4];
        float lp = 0.f;
        #pragma unroll
        for (int j = 0; j < 4; j++) {
            sf[j] = sp[j];
            float4 av = *(const float4*)&s_alpha[g * 16 + j * 4];
            lp += sf[j].x * av.x + sf[j].y * av.y + sf[j].z * av.z + sf[j].w * av.w;
        }
        lp += __shfl_xor_sync(0xffffffffu, lp, 1);
        lp += __shfl_xor_sync(0xffffffffu, lp, 2);
        lp += __shfl_xor_sync(0xffffffffu, lp, 4);

        int ji[S];
        #pragma unroll
        for (int s = 0; s < S; s++) ji[s] = neigh_idx[row * S + s];
        float att[S], asum = 0.f;
        #pragma unroll
        for (int s = 0; s < S; s++) {
            float lgt = fmaxf(lp + g_ln[ji[s]], 0.f);
            att[s] = __expf(lgt);
            asum += att[s];
        }
        const float inv = 1.f / asum;

        float4 agg[4];
        #pragma unroll
        for (int j = 0; j < 4; j++) agg[j] = make_float4(0.f, 0.f, 0.f, 0.f);
        #pragma unroll
        for (int s = 0; s < S; s++) {
            const float wt = att[s] * inv;
            const float4* pp = (const float4*)(g_pre + (size_t)ji[s] * F + g * 16);
            #pragma unroll
            for (int j = 0; j < 4; j++) {
                float4 v = pp[j];
                agg[j].x += wt * v.x;  agg[j].y += wt * v.y;
                agg[j].z += wt * v.z;  agg[j].w += wt * v.w;
            }
        }

        #pragma unroll
        for (int j = 0; j < 4; j++) {
            float4 a, b;
            a.x = __uint_as_float(tf32cvt(sf[j].x));
            a.y = __uint_as_float(tf32cvt(sf[j].y));
            a.z = __uint_as_float(tf32cvt(sf[j].z));
            a.w = __uint_as_float(tf32cvt(sf[j].w));
            b.x = __uint_as_float(tf32cvt(agg[j].x));
            b.y = __uint_as_float(tf32cvt(agg[j].y));
            b.z = __uint_as_float(tf32cvt(agg[j].z));
            b.w = __uint_as_float(tf32cvt(agg[j].w));
            *(float4*)&s_comb[r * CS + g * 16 + j * 4]       = a;
            *(float4*)&s_comb[r * CS + 128 + g * 16 + j * 4] = b;
        }
    }
    __syncthreads();

    // ---- phase 2: TF32 MMA ----
    {
        const int lane = tid & 31, w = tid >> 5;
        float d[2][2][4];
        #pragma unroll
        for (int mt = 0; mt < 2; mt++)
            #pragma unroll
            for (int nt = 0; nt < 2; nt++)
                #pragma unroll
                for (int i = 0; i < 4; i++) d[mt][nt][i] = 0.f;

        const uint32_t* wB = &g_wB[((size_t)w * 32 + lane) * 4];
        const int arow = lane >> 2, acol = lane & 3;

        #pragma unroll 4
        for (int kt = 0; kt < 32; kt++) {
            uint4 b = *(const uint4*)(wB + (size_t)kt * 1024);
            const int kc = kt * 8 + acol;
            #pragma unroll
            for (int mt = 0; mt < 2; mt++) {
                const float* ap = &s_comb[(mt * 16 + arow) * CS + kc];
                uint32_t a[4];
                a[0] = __float_as_uint(ap[0]);
                a[1] = __float_as_uint(ap[8 * CS]);
                a[2] = __float_as_uint(ap[4]);
                a[3] = __float_as_uint(ap[8 * CS + 4]);
                mma_tf32(d[mt][0], a, b.x, b.y);
                mma_tf32(d[mt][1], a, b.z, b.w);
            }
        }

        #pragma unroll
        for (int mt = 0; mt < 2; mt++) {
            #pragma unroll
            for (int nt = 0; nt < 2; nt++) {
                int R = mt * 16 + (lane >> 2);
                int C = w * 16 + nt * 8 + (lane & 3) * 2;
                int m = m0 + R;
                if (m < B) {
                    float2 o;
                    o.x = fmaxf(d[mt][nt][0], 0.f);
                    o.y = fmaxf(d[mt][nt][1], 0.f);
                    *(float2*)&out[(size_t)m * F + C] = o;
                }
                if (m + 8 < B) {
                    float2 o;
                    o.x = fmaxf(d[mt][nt][2], 0.f);
                    o.y = fmaxf(d[mt][nt][3], 0.f);
                    *(float2*)&out[(size_t)(m + 8) * F + C] = o;
                }
            }
        }
    }
}

#define FUSED_SMEM ((32 * CS + 128) * 4)

// ---------------------------------------------------------------------------
extern "C" void kernel_launch(void* const* d_in, const int* in_sizes, int n_in,
                              void* d_out, int out_size) {
    const int*   nodes        = (const int*)d_in[0];
    const int*   neigh_idx    = (const int*)d_in[1];
    const float* self_table   = (const float*)d_in[2];
    const float* neigh_table  = (const float*)d_in[3];
    const float* center       = (const float*)d_in[4];
    const float* cluster_mask = (const float*)d_in[5];
    const float* weight       = (const float*)d_in[6];
    const float* alpha        = (const float*)d_in[7];
    float* out = (float*)d_out;

    int B = in_sizes[0];
    int N = in_sizes[3] / F;

    cudaFuncSetAttribute(precompute_kernel,
                         cudaFuncAttributeMaxDynamicSharedMemorySize, A_SMEM);
    cudaFuncSetAttribute(fused_kernel,
                         cudaFuncAttributeMaxDynamicSharedMemorySize, FUSED_SMEM);

    encode_consts<<<145, 256>>>(weight, center, cluster_mask);
    precompute_kernel<<<(N + 127) / 128, 256, A_SMEM>>>(neigh_table, alpha, N);
    fused_kernel<<<(B + 31) / 32, 256, FUSED_SMEM>>>(nodes, neigh_idx,
                                                     self_table, alpha, out, B);
}

// round 10
// speedup vs baseline: 1.8585x; 1.0367x over previous
#include <cuda_runtime.h>
#include <math.h>
#include <stdint.h>

#define F   128
#define S   10
#define KC  16
#define MAXN 200000
#define MAXB 20000

typedef unsigned long long ull;

// static scratch (allocation-free rule)
__device__ float    g_pre[(size_t)MAXN * F];  // t_j * (q_j @ mask)
__device__ float    g_ln[MAXN];               // t_j . a_neigh
__device__ uint32_t g_wB[32 * 8 * 32 * 4];    // weight tf32 B-frags (out GEMM)
__device__ uint32_t g_cB[16 * 32 * 4];        // center tf32 B-frags (cross)
__device__ uint32_t g_mB[16 * 32 * 4];        // mask tf32 B-frags (maskMM)
__device__ float    g_c2[16];                 // |center_k|^2

// ---- packed f32x2 helpers ----
__device__ __forceinline__ ull ffma2(ull a, ull b, ull c) {
    ull d; asm("fma.rn.f32x2 %0,%1,%2,%3;" : "=l"(d) : "l"(a), "l"(b), "l"(c)); return d;
}
__device__ __forceinline__ float2 funpack(ull a) {
    float2 f; asm("mov.b64 {%0,%1},%2;" : "=f"(f.x), "=f"(f.y) : "l"(a)); return f;
}
__device__ __forceinline__ float fsum2(ull a) { float2 f = funpack(a); return f.x + f.y; }

__device__ __forceinline__ uint32_t tf32cvt(float x) {
    uint32_t u; asm("cvt.rna.tf32.f32 %0,%1;" : "=r"(u) : "f"(x)); return u;
}
__device__ __forceinline__ void mma_tf32(float* d, const uint32_t* a,
                                         uint32_t b0, uint32_t b1) {
    asm("mma.sync.aligned.m16n8k8.row.col.f32.tf32.tf32.f32 "
        "{%0,%1,%2,%3},{%4,%5,%6,%7},{%8,%9},{%0,%1,%2,%3};"
        : "+f"(d[0]), "+f"(d[1]), "+f"(d[2]), "+f"(d[3])
        : "r"(a[0]), "r"(a[1]), "r"(a[2]), "r"(a[3]), "r"(b0), "r"(b1));
}

// ---------------------------------------------------------------------------
// Kernel E: encode all constants (weight/center/mask B-frags + c2). One-time.
// ---------------------------------------------------------------------------
__global__ void encode_consts(const float* __restrict__ weight,
                              const float* __restrict__ center,
                              const float* __restrict__ cluster_mask) {
    int idx = blockIdx.x * 256 + threadIdx.x;
    if (idx < 32768) {                      // weight B-frags (verified R6)
        int sub = idx & 3, lane = (idx >> 2) & 31;
        int ntp = (idx >> 7) & 7, kt = idx >> 10;
        int n = ntp * 16 + (sub >> 1) * 8 + (lane >> 2);
        int k = kt * 8 + (lane & 3) + (sub & 1) * 4;
        g_wB[idx] = tf32cvt(weight[n * 256 + k]);
    } else if (idx < 34816) {               // center B-frags: b = C[n][k]
        int j = idx - 32768;
        int sub = j & 3, lane = (j >> 2) & 31, kt = j >> 7;   // kt 0..15
        int n = (sub >> 1) * 8 + (lane >> 2);                 // nt = sub>>1
        int k = kt * 8 + (lane & 3) + (sub & 1) * 4;
        g_cB[j] = tf32cvt(center[n * F + k]);
    } else if (idx < 36864) {               // mask B-frags: b = mask[k][n]
        int j = idx - 34816;
        int sub = j & 3, lane = (j >> 2) & 31, nt = j >> 7;   // nt 0..15
        int n = nt * 8 + (lane >> 2);
        int k = (sub >> 1) * 8 + (lane & 3) + (sub & 1) * 4;  // kt = sub>>1
        g_mB[j] = tf32cvt(cluster_mask[k * F + n]);
    } else if (idx < 36880) {               // c2
        int k = idx - 36864;
        float a = 0.f;
        for (int f = 0; f < F; f++) { float c = center[k * F + f]; a += c * c; }
        g_c2[k] = a;
    }
}

// ---------------------------------------------------------------------------
// Kernel A: precompute via tensor cores. grid = ceil(N/128), block = 256.
// Warp w owns M-strip rows [w*16, w*16+16). cross & maskMM on tf32 MMA;
// n2/ln fp32. q redistributed intra-warp via shfl (no s_Q) -> 3 blocks/SM.
// ---------------------------------------------------------------------------
#define PTS 132

__global__ void __launch_bounds__(256, 3)
precompute_kernel(const float* __restrict__ neigh_table,
                  const float* __restrict__ alpha,
                  int N) {
    extern __shared__ float sm[];
    float* s_T  = sm;                       // [128][PTS]
    float* s_an = sm + 128 * PTS;           // [128]
    float* s_n2 = s_an + 128;               // [128]
    float* s_c2 = s_n2 + 128;               // [16]

    const int tid = threadIdx.x;
    const int rowbase = blockIdx.x * 128;

    if (tid < 32) ((float4*)s_an)[tid] = ((const float4*)alpha)[32 + tid];  // a_neigh
    if (tid < 16) s_c2[tid] = g_c2[tid];

    #pragma unroll
    for (int it = 0; it < 16; it++) {       // coalesced tile load
        int e = it * 256 + tid;
        int r = e >> 5, c4 = e & 31;
        int grow = min(rowbase + r, N - 1);
        float4 v = *(const float4*)&neigh_table[(size_t)grow * F + c4 * 4];
        *(float4*)&s_T[r * PTS + c4 * 4] = v;
    }
    __syncthreads();

    // ---- n2 / ln (fp32): thread = (row tid>>1, half tid&1) ----
    {
        const int r = tid >> 1, h = tid & 1;
        const float* xb = &s_T[r * PTS + h * 64];
        const float* ab = &s_an[h * 64];
        ull n2 = 0ull, ln = 0ull;
        #pragma unroll 4
        for (int ch = 0; ch < 16; ch++) {
            ulonglong2 x = *(const ulonglong2*)&xb[ch * 4];
            ulonglong2 a = *(const ulonglong2*)&ab[ch * 4];
            n2 = ffma2(x.x, x.x, n2);  n2 = ffma2(x.y, x.y, n2);
            ln = ffma2(x.x, a.x, ln);  ln = ffma2(x.y, a.y, ln);
        }
        float n2f = fsum2(n2), lnf = fsum2(ln);
        n2f += __shfl_xor_sync(0xffffffffu, n2f, 1);
        lnf += __shfl_xor_sync(0xffffffffu, lnf, 1);
        if (h == 0) {
            s_n2[r] = n2f;
            g_ln[min(rowbase + r, N - 1)] = lnf;
        }
    }

    const int l = tid & 31, w = tid >> 5;
    const int r0 = w * 16 + (l >> 2);       // lane row (and r0+8)
    const int c  = l & 3;

    // ---- cross = T @ C^T via MMA: 16 kt, N=16 (2 n-tiles) ----
    float d[2][4];
    #pragma unroll
    for (int nt = 0; nt < 2; nt++)
        #pragma unroll
        for (int i = 0; i < 4; i++) d[nt][i] = 0.f;

    #pragma unroll 4
    for (int kt = 0; kt < 16; kt++) {
        uint4 bc = *(const uint4*)&g_cB[(kt * 32 + l) * 4];
        const float* ap = &s_T[r0 * PTS + kt * 8 + c];
        uint32_t a[4];
        a[0] = tf32cvt(ap[0]);
        a[1] = tf32cvt(ap[8 * PTS]);
        a[2] = tf32cvt(ap[4]);
        a[3] = tf32cvt(ap[8 * PTS + 4]);
        mma_tf32(d[0], a, bc.x, bc.y);
        mma_tf32(d[1], a, bc.z, bc.w);
    }
    __syncthreads();                        // s_n2 ready

    // ---- q epilogue in registers: lane owns rows {r0, r0+8} x cols
    //      {nt*8+2c, nt*8+2c+1} ----
    float qv[2][4];
    {
        const float n2A = s_n2[r0], n2B = s_n2[r0 + 8];
        #pragma unroll
        for (int nt = 0; nt < 2; nt++) {
            int k0 = nt * 8 + 2 * c;
            float c2a = s_c2[k0] + 1.f, c2b = s_c2[k0 + 1] + 1.f;
            qv[nt][0] = 1.f / (n2A - 2.f * d[nt][0] + c2a);
            qv[nt][1] = 1.f / (n2A - 2.f * d[nt][1] + c2b);
            qv[nt][2] = 1.f / (n2B - 2.f * d[nt][2] + c2a);
            qv[nt][3] = 1.f / (n2B - 2.f * d[nt][3] + c2b);
        }
    }

    // ---- intra-warp redistribution to maskMM A-frag layout (no smem) ----
    // aq[kt][0]=q(rA,kt*8+c)  [1]=q(rB,same)  [2]=q(rA,kt*8+c+4)  [3]=q(rB,..)
    // owner of col x is lane (l&~3)|(x>>1), element parity x&1.
    uint32_t aq[2][4];
    {
        const unsigned FULLM = 0xffffffffu;
        const int ls1 = (l & ~3) | (c >> 1);
        const int ls2 = ls1 + 2;
        const bool odd = (c & 1) != 0;
        #pragma unroll
        for (int kt = 0; kt < 2; kt++) {
            float a0 = __shfl_sync(FULLM, qv[kt][0], ls1);
            float a1 = __shfl_sync(FULLM, qv[kt][1], ls1);
            float b0 = __shfl_sync(FULLM, qv[kt][2], ls1);
            float b1 = __shfl_sync(FULLM, qv[kt][3], ls1);
            float e0 = __shfl_sync(FULLM, qv[kt][0], ls2);
            float e1 = __shfl_sync(FULLM, qv[kt][1], ls2);
            float f0 = __shfl_sync(FULLM, qv[kt][2], ls2);
            float f1 = __shfl_sync(FULLM, qv[kt][3], ls2);
            aq[kt][0] = tf32cvt(odd ? a1 : a0);
            aq[kt][1] = tf32cvt(odd ? b1 : b0);
            aq[kt][2] = tf32cvt(odd ? e1 : e0);
            aq[kt][3] = tf32cvt(odd ? f1 : f0);
        }
    }

    const int growA = min(rowbase + r0, N - 1);
    const int growB = min(rowbase + r0 + 8, N - 1);

    // ---- m = q @ mask via MMA; pre = T * m; store ----
    #pragma unroll 4
    for (int nt = 0; nt < 16; nt++) {
        uint4 bm = *(const uint4*)&g_mB[(nt * 32 + l) * 4];
        float dm[4] = {0.f, 0.f, 0.f, 0.f};
        mma_tf32(dm, aq[0], bm.x, bm.y);
        mma_tf32(dm, aq[1], bm.z, bm.w);

        int col = nt * 8 + 2 * c;
        float2 tA = *(const float2*)&s_T[r0 * PTS + col];
        float2 tB = *(const float2*)&s_T[(r0 + 8) * PTS + col];
        float2 oA, oB;
        oA.x = tA.x * dm[0];  oA.y = tA.y * dm[1];
        oB.x = tB.x * dm[2];  oB.y = tB.y * dm[3];
        *(float2*)&g_pre[(size_t)growA * F + col] = oA;
        *(float2*)&g_pre[(size_t)growB * F + col] = oB;
    }
}

#define A_SMEM ((128 * PTS + 128 + 128 + 16) * 4)

// ---------------------------------------------------------------------------
// Kernel B: fused gather + attention + TF32 MMA GEMM (verified R7/R8).
// ---------------------------------------------------------------------------
#define CS 268

__global__ void __launch_bounds__(256, 3)
fused_kernel(const int* __restrict__ nodes,
             const int* __restrict__ neigh_idx,
             const float* __restrict__ self_table,
             const float* __restrict__ alpha,
             float* __restrict__ out, int B) {
    extern __shared__ float smf[];
    float* s_comb  = smf;             // [32][CS] tf32-bit floats
    float* s_alpha = smf + 32 * CS;   // [128]

    const int tid = threadIdx.x;
    if (tid < 32) ((float4*)s_alpha)[tid] = ((const float4*)alpha)[tid];  // a_self
    __syncthreads();

    const int m0 = blockIdx.x * 32;

    // ---- phase 1: gather + attention ----
    {
        const int r = tid >> 3, g = tid & 7;
        const int row = min(m0 + r, B - 1);
        const int node = nodes[row];
        const float4* sp = (const float4*)(self_table + (size_t)node * F + g * 16);
        float4 sf[4];
        float lp = 0.f;
        #pragma unroll
        for (int j = 0; j < 4; j++) {
            sf[j] = sp[j];
            float4 av = *(const float4*)&s_alpha[g * 16 + j * 4];
            lp += sf[j].x * av.x + sf[j].y * av.y + sf[j].z * av.z + sf[j].w * av.w;
        }
        lp += __shfl_xor_sync(0xffffffffu, lp, 1);
        lp += __shfl_xor_sync(0xffffffffu, lp, 2);
        lp += __shfl_xor_sync(0xffffffffu, lp, 4);

        int ji[S];
        #pragma unroll
        for (int s = 0; s < S; s++) ji[s] = neigh_idx[row * S + s];
        float att[S], asum = 0.f;
        #pragma unroll
        for (int s = 0; s < S; s++) {
            float lgt = fmaxf(lp + g_ln[ji[s]], 0.f);
            att[s] = __expf(lgt);
            asum += att[s];
        }
        const float inv = 1.f / asum;

        float4 agg[4];
        #pragma unroll
        for (int j = 0; j < 4; j++) agg[j] = make_float4(0.f, 0.f, 0.f, 0.f);
        #pragma unroll
        for (int s = 0; s < S; s++) {
            const float wt = att[s] * inv;
            const float4* pp = (const float4*)(g_pre + (size_t)ji[s] * F + g * 16);
            #pragma unroll
            for (int j = 0; j < 4; j++) {
                float4 v = pp[j];
                agg[j].x += wt * v.x;  agg[j].y += wt * v.y;
                agg[j].z += wt * v.z;  agg[j].w += wt * v.w;
            }
        }

        #pragma unroll
        for (int j = 0; j < 4; j++) {
            float4 a, b;
            a.x = __uint_as_float(tf32cvt(sf[j].x));
            a.y = __uint_as_float(tf32cvt(sf[j].y));
            a.z = __uint_as_float(tf32cvt(sf[j].z));
            a.w = __uint_as_float(tf32cvt(sf[j].w));
            b.x = __uint_as_float(tf32cvt(agg[j].x));
            b.y = __uint_as_float(tf32cvt(agg[j].y));
            b.z = __uint_as_float(tf32cvt(agg[j].z));
            b.w = __uint_as_float(tf32cvt(agg[j].w));
            *(float4*)&s_comb[r * CS + g * 16 + j * 4]       = a;
            *(float4*)&s_comb[r * CS + 128 + g * 16 + j * 4] = b;
        }
    }
    __syncthreads();

    // ---- phase 2: TF32 MMA ----
    {
        const int lane = tid & 31, w = tid >> 5;
        float d[2][2][4];
        #pragma unroll
        for (int mt = 0; mt < 2; mt++)
            #pragma unroll
            for (int nt = 0; nt < 2; nt++)
                #pragma unroll
                for (int i = 0; i < 4; i++) d[mt][nt][i] = 0.f;

        const uint32_t* wB = &g_wB[((size_t)w * 32 + lane) * 4];
        const int arow = lane >> 2, acol = lane & 3;

        #pragma unroll 4
        for (int kt = 0; kt < 32; kt++) {
            uint4 b = *(const uint4*)(wB + (size_t)kt * 1024);
            const int kc = kt * 8 + acol;
            #pragma unroll
            for (int mt = 0; mt < 2; mt++) {
                const float* ap = &s_comb[(mt * 16 + arow) * CS + kc];
                uint32_t a[4];
                a[0] = __float_as_uint(ap[0]);
                a[1] = __float_as_uint(ap[8 * CS]);
                a[2] = __float_as_uint(ap[4]);
                a[3] = __float_as_uint(ap[8 * CS + 4]);
                mma_tf32(d[mt][0], a, b.x, b.y);
                mma_tf32(d[mt][1], a, b.z, b.w);
            }
        }

        #pragma unroll
        for (int mt = 0; mt < 2; mt++) {
            #pragma unroll
            for (int nt = 0; nt < 2; nt++) {
                int R = mt * 16 + (lane >> 2);
                int C = w * 16 + nt * 8 + (lane & 3) * 2;
                int m = m0 + R;
                if (m < B) {
                    float2 o;
                    o.x = fmaxf(d[mt][nt][0], 0.f);
                    o.y = fmaxf(d[mt][nt][1], 0.f);
                    *(float2*)&out[(size_t)m * F + C] = o;
                }
                if (m + 8 < B) {
                    float2 o;
                    o.x = fmaxf(d[mt][nt][2], 0.f);
                    o.y = fmaxf(d[mt][nt][3], 0.f);
                    *(float2*)&out[(size_t)(m + 8) * F + C] = o;
                }
            }
        }
    }
}

#define FUSED_SMEM ((32 * CS + 128) * 4)

// ---------------------------------------------------------------------------
extern "C" void kernel_launch(void* const* d_in, const int* in_sizes, int n_in,
                              void* d_out, int out_size) {
    const int*   nodes        = (const int*)d_in[0];
    const int*   neigh_idx    = (const int*)d_in[1];
    const float* self_table   = (const float*)d_in[2];
    const float* neigh_table  = (const float*)d_in[3];
    const float* center       = (const float*)d_in[4];
    const float* cluster_mask = (const float*)d_in[5];
    const float* weight       = (const float*)d_in[6];
    const float* alpha        = (const float*)d_in[7];
    float* out = (float*)d_out;

    int B = in_sizes[0];
    int N = in_sizes[3] / F;

    cudaFuncSetAttribute(precompute_kernel,
                         cudaFuncAttributeMaxDynamicSharedMemorySize, A_SMEM);
    cudaFuncSetAttribute(fused_kernel,
                         cudaFuncAttributeMaxDynamicSharedMemorySize, FUSED_SMEM);

    encode_consts<<<145, 256>>>(weight, center, cluster_mask);
    precompute_kernel<<<(N + 127) / 128, 256, A_SMEM>>>(neigh_table, alpha, N);
    fused_kernel<<<(B + 31) / 32, 256, FUSED_SMEM>>>(nodes, neigh_idx,
                                                     self_table, alpha, out, B);
}